// round 9
// baseline (speedup 1.0000x reference)
#include <cuda_runtime.h>
#include <cstdint>
#include <cstddef>

#define NB 16
#define NP 4096
#define NS 1024
#define NK 16
#define NF 256
#define NO 512
#define NPTS (NB*NP)
#define NQ   (NB*NS)
#define SEG  4
#define PSEG (NP/SEG)

#define POS_INF __int_as_float(0x7f800000)
#define NEG_INF __int_as_float(0xff800000)

typedef unsigned long long u64;

__device__ float g_h[(size_t)NPTS * NO];
__device__ float g_hn[NPTS];
__device__ int   g_fps[NQ];
__device__ float g_part[2 * 128 * NO];
__device__ float g_a[NO];
__device__ float g_c[NO];
__device__ float g_knnv[(size_t)NQ * SEG * NK];
__device__ int   g_knni[(size_t)NQ * SEG * NK];
__device__ int   g_nn[(size_t)NQ * NK];

// ---------------- f32x2 helpers (each half rounds exactly like scalar FFMA) --
__device__ __forceinline__ u64 dup2(float x) {
    u64 r;
    uint32_t b = __float_as_uint(x);
    asm("mov.b64 %0, {%1, %1};" : "=l"(r) : "r"(b));
    return r;
}
#define FMA2(acc, a, b) \
    asm("fma.rn.f32x2 %0, %1, %2, %0;" : "+l"(acc) : "l"(a), "l"(b))
__device__ __forceinline__ float2 unpack2(u64 v) {
    float2 r;
    asm("mov.b64 {%0, %1}, %2;" : "=f"(r.x), "=f"(r.y) : "l"(v));
    return r;
}

// B-dup swizzled layout: value for col c, chunk-row k lives (as a {b,b} u64) at
// byte offset k*1088 + (c&7)*136 + (c>>3)*8. Reads (j fixed, tx 0..15) are a
// contiguous 128B line -> 1 wavefront, conflict-free.
#define BDUP_K 1088
__device__ __forceinline__ int bdup_off(int c) { return (c & 7) * 136 + (c >> 3) * 8; }

// ===================== K1: fused FPS + MLP-GEMM + xnorm ======================
#define FPS_SMEM_BYTES ((NP * 3 + NS + 8 + 8 + 1) * 4)
#define GEMM_A_BYTES (2 * 8 * 128 * 4)     // 2 stages col-major A
#define GEMM_B_BYTES (2 * 8 * BDUP_K)      // 2 stages dup B
#define FUSED_SMEM (FPS_SMEM_BYTES)        // 53.3KB > 25.6KB GEMM need

__device__ void fps_body(char* smc, const float* __restrict__ positions,
                         const int* __restrict__ batch,
                         float* __restrict__ out_pos, float* __restrict__ out_batch,
                         int cloud) {
    float* spos  = (float*)smc;
    int*   sel   = (int*)(spos + NP * 3);
    float* rv    = (float*)(sel + NS);
    int*   ri    = (int*)(rv + 8);
    int*   slast = ri + 8;
    const int tid = threadIdx.x;
    const float* pos = positions + (size_t)cloud * NP * 3;
    for (int i = tid; i < NP * 3; i += 256) spos[i] = pos[i];
    __syncthreads();

    float px[16], py[16], pz[16], md[16];
#pragma unroll
    for (int j = 0; j < 16; j++) {
        int pt = tid + j * 256;
        px[j] = spos[pt * 3]; py[j] = spos[pt * 3 + 1]; pz[j] = spos[pt * 3 + 2];
        md[j] = POS_INF;
    }
    if (tid == 0) sel[0] = 0;
    int last = 0;
    const int lane = tid & 31, warp = tid >> 5;
    for (int it = 1; it < NS; it++) {
        float lx = spos[last * 3], ly = spos[last * 3 + 1], lz = spos[last * 3 + 2];
        float bv = NEG_INF; int bi = 0x7fffffff;
#pragma unroll
        for (int j = 0; j < 16; j++) {
            float dx = px[j] - lx, dy = py[j] - ly, dz = pz[j] - lz;
            float d = __fadd_rn(__fadd_rn(__fmul_rn(dx, dx), __fmul_rn(dy, dy)),
                                __fmul_rn(dz, dz));
            float m = fminf(md[j], d);
            md[j] = m;
            if (m > bv) { bv = m; bi = tid + j * 256; }
        }
#pragma unroll
        for (int off = 16; off > 0; off >>= 1) {
            float ov = __shfl_down_sync(0xffffffffu, bv, off);
            int   oi = __shfl_down_sync(0xffffffffu, bi, off);
            if (ov > bv || (ov == bv && oi < bi)) { bv = ov; bi = oi; }
        }
        if (lane == 0) { rv[warp] = bv; ri[warp] = bi; }
        __syncthreads();
        if (warp == 0) {
            float v = (lane < 8) ? rv[lane] : NEG_INF;
            int b = (lane < 8) ? ri[lane] : 0x7fffffff;
#pragma unroll
            for (int off = 4; off > 0; off >>= 1) {
                float ov = __shfl_down_sync(0xffffffffu, v, off);
                int   oi = __shfl_down_sync(0xffffffffu, b, off);
                if (ov > v || (ov == v && oi < b)) { v = ov; b = oi; }
            }
            if (lane == 0) { sel[it] = b; slast[0] = b; }
        }
        __syncthreads();
        last = slast[0];
    }
    for (int s = tid; s < NS; s += 256) {
        int loc = sel[s], g = cloud * NP + loc, oq = cloud * NS + s;
        g_fps[oq] = g;
        out_pos[oq * 3 + 0] = spos[loc * 3 + 0];
        out_pos[oq * 3 + 1] = spos[loc * 3 + 1];
        out_pos[oq * 3 + 2] = spos[loc * 3 + 2];
        out_batch[oq] = (float)batch[g];
    }
}

__global__ __launch_bounds__(256, 2) void fused_kernel(
    const float* __restrict__ A, const float* __restrict__ positions,
    const int* __restrict__ batch, const float* __restrict__ W,
    const float* __restrict__ bias,
    float* __restrict__ out_pos, float* __restrict__ out_batch) {
    extern __shared__ __align__(16) char smc[];
    if (blockIdx.x < 16) {
        fps_body(smc, positions, batch, out_pos, out_batch, blockIdx.x);
        return;
    }
    const int b = blockIdx.x - 16;
    const int bx = b & 3, by = b >> 2;
    float* As = (float*)smc;                  // [2][8][128] col-major
    char*  Wm = smc + GEMM_A_BYTES;           // [2][8 x 1088B] dup
    const int tid = threadIdx.x;
    const int tx = tid & 15, ty = tid >> 4;
    const int arow = tid >> 1, acol = (tid & 1) * 4;
    const int brow = tid >> 5, bcol = (tid & 31) * 4;
    const float* aptr = A + (size_t)(by * 128 + arow) * NF + acol;
    const float* wbase = W + (size_t)brow * NO + bx * 128 + bcol;

    u64 acc2[4][8];
#pragma unroll
    for (int ip = 0; ip < 4; ip++)
#pragma unroll
        for (int j = 0; j < 8; j++) acc2[ip][j] = 0ull;
    float sq = 0.f;

    float4 av = *(const float4*)aptr;
    float4 wv = *(const float4*)wbase;
    for (int kb = 0; kb < 32; kb++) {
        float* Asb = As + (kb & 1) * 1024;
        char*  Wsb = Wm + (kb & 1) * 8 * BDUP_K;
        Asb[(acol + 0) * 128 + arow] = av.x;
        Asb[(acol + 1) * 128 + arow] = av.y;
        Asb[(acol + 2) * 128 + arow] = av.z;
        Asb[(acol + 3) * 128 + arow] = av.w;
        {
            char* wrow = Wsb + brow * BDUP_K;
            *(u64*)(wrow + bdup_off(bcol + 0)) = dup2(wv.x);
            *(u64*)(wrow + bdup_off(bcol + 1)) = dup2(wv.y);
            *(u64*)(wrow + bdup_off(bcol + 2)) = dup2(wv.z);
            *(u64*)(wrow + bdup_off(bcol + 3)) = dup2(wv.w);
        }
        if (bx == 0) {
            sq = fmaf(av.x, av.x, sq); sq = fmaf(av.y, av.y, sq);
            sq = fmaf(av.z, av.z, sq); sq = fmaf(av.w, av.w, sq);
        }
        __syncthreads();
        if (kb < 31) {
            av = *(const float4*)(aptr + (kb + 1) * 8);
            wv = *(const float4*)(wbase + (size_t)(kb + 1) * 8 * NO);
        }
#pragma unroll
        for (int k = 0; k < 8; k++) {
            u64 a2[4], bd[8];
#pragma unroll
            for (int ip = 0; ip < 4; ip++)
                a2[ip] = *(const u64*)&Asb[k * 128 + ty * 8 + ip * 2];
            const char* wrow = Wsb + k * BDUP_K;
#pragma unroll
            for (int j = 0; j < 8; j++)
                bd[j] = *(const u64*)(wrow + j * 136 + tx * 8);
#pragma unroll
            for (int ip = 0; ip < 4; ip++)
#pragma unroll
                for (int j = 0; j < 8; j++)
                    FMA2(acc2[ip][j], a2[ip], bd[j]);
        }
        __syncthreads();
    }

    if (bx == 0) {
        float o = __shfl_xor_sync(0xffffffffu, sq, 1);
        if ((tid & 1) == 0) g_hn[by * 128 + arow] = 0.5f * (sq + o);
    }

    const int ccol = bx * 128 + tx * 8;
    const int crow = by * 128 + ty * 8;
    float4 bb0 = *(const float4*)(bias + ccol);
    float4 bb1 = *(const float4*)(bias + ccol + 4);
    const float* bb = &bb0.x;
#pragma unroll
    for (int ip = 0; ip < 4; ip++) {
        float r0[8], r1[8];
#pragma unroll
        for (int j = 0; j < 8; j++) {
            float2 p = unpack2(acc2[ip][j]);
            float bj = (j < 4) ? bb[j] : (&bb1.x)[j - 4];
            r0[j] = p.x + bj;
            r1[j] = p.y + bj;
        }
        float* o0 = g_h + (size_t)(crow + ip * 2) * NO + ccol;
        float* o1 = g_h + (size_t)(crow + ip * 2 + 1) * NO + ccol;
        *(float4*)o0 = make_float4(r0[0], r0[1], r0[2], r0[3]);
        *(float4*)(o0 + 4) = make_float4(r0[4], r0[5], r0[6], r0[7]);
        *(float4*)o1 = make_float4(r1[0], r1[1], r1[2], r1[3]);
        *(float4*)(o1 + 4) = make_float4(r1[4], r1[5], r1[6], r1[7]);
    }
}

// ===================== BN stats =====================
__global__ __launch_bounds__(512) void stats_partial_kernel() {
    int c = threadIdx.x, blk = blockIdx.x;
    float s = 0.f, s2 = 0.f;
    int r0 = blk * 512;
    for (int r = 0; r < 512; r++) {
        float v = g_h[(size_t)(r0 + r) * NO + c];
        s += v; s2 = fmaf(v, v, s2);
    }
    g_part[blk * NO + c] = s;
    g_part[128 * NO + blk * NO + c] = s2;
}
__global__ __launch_bounds__(512) void stats_final_kernel(const float* __restrict__ gamma,
                                                          const float* __restrict__ beta) {
    int c = threadIdx.x;
    float s = 0.f, s2 = 0.f;
    for (int b = 0; b < 128; b++) { s += g_part[b * NO + c]; s2 += g_part[128 * NO + b * NO + c]; }
    float inv = 1.0f / (float)NPTS;
    float mu = s * inv, var = s2 * inv - mu * mu;
    float a = gamma[c] * rsqrtf(var + 1e-5f);
    g_a[c] = a; g_c[c] = beta[c] - mu * a;
}

// ===================== KNN: conflict-free f32x2 GEMM + top-16 ================
#define K_QS 0
#define K_XS (K_QS + 2*8*128*4)            // 8192
#define K_SC (K_XS + 2*8*BDUP_K)           // 25600
#define K_HN (K_SC + 128*129*4)            // 91648
#define K_TV (K_HN + 128*4)                // 92160
#define K_TI (K_TV + 128*NK*4)             // 100352
#define KNN_SMEM (K_TI + 128*NK*4)         // 108544 -> 2 blocks/SM

__global__ __launch_bounds__(256, 2) void knn_kernel(const float* __restrict__ feat) {
    extern __shared__ __align__(16) char smc[];
    float* Qs   = (float*)(smc + K_QS);
    char*  Xm   = smc + K_XS;
    float* Sc   = (float*)(smc + K_SC);
    float* hn_s = (float*)(smc + K_HN);
    float* topv = (float*)(smc + K_TV);
    int*   topi = (int*)(smc + K_TI);

    const int qt = blockIdx.x, sg = blockIdx.y, cloud = blockIdx.z;
    const int tid = threadIdx.x;
    const int tx = tid & 15, ty = tid >> 4;
    const int arow = tid >> 1, acol = (tid & 1) * 4;

    const int qr = g_fps[cloud * NS + qt * 128 + arow];
    const float* qptr = feat + (size_t)qr * NF + acol;

    if (tid < 128) {
#pragma unroll
        for (int r = 0; r < NK; r++) {
            topv[tid * NK + r] = NEG_INF;
            topi[tid * NK + r] = 0x7fffffff;
        }
    }
    const int xcloudbase = cloud * NP + sg * PSEG;
    __syncthreads();

    for (int t = 0; t < PSEG / 128; t++) {
        const int xbase = xcloudbase + t * 128;
        if (tid < 128) hn_s[tid] = g_hn[xbase + tid];
        const float* xptr = feat + (size_t)(xbase + arow) * NF + acol;

        u64 acc2[4][8];
#pragma unroll
        for (int ip = 0; ip < 4; ip++)
#pragma unroll
            for (int j = 0; j < 8; j++) acc2[ip][j] = 0ull;

        float4 qv = *(const float4*)qptr;
        float4 xv = *(const float4*)xptr;
        for (int kb = 0; kb < 32; kb++) {
            float* Qsb = Qs + (kb & 1) * 1024;
            char*  Xsb = Xm + (kb & 1) * 8 * BDUP_K;
            Qsb[(acol + 0) * 128 + arow] = qv.x;
            Qsb[(acol + 1) * 128 + arow] = qv.y;
            Qsb[(acol + 2) * 128 + arow] = qv.z;
            Qsb[(acol + 3) * 128 + arow] = qv.w;
            {
                int co = bdup_off(arow);        // x row index = col of B operand
                *(u64*)(Xsb + (acol + 0) * BDUP_K + co) = dup2(xv.x);
                *(u64*)(Xsb + (acol + 1) * BDUP_K + co) = dup2(xv.y);
                *(u64*)(Xsb + (acol + 2) * BDUP_K + co) = dup2(xv.z);
                *(u64*)(Xsb + (acol + 3) * BDUP_K + co) = dup2(xv.w);
            }
            __syncthreads();
            if (kb < 31) {
                qv = *(const float4*)(qptr + (kb + 1) * 8);
                xv = *(const float4*)(xptr + (kb + 1) * 8);
            }
#pragma unroll
            for (int k = 0; k < 8; k++) {
                u64 a2[4], bd[8];
#pragma unroll
                for (int ip = 0; ip < 4; ip++)
                    a2[ip] = *(const u64*)&Qsb[k * 128 + ty * 8 + ip * 2];
                const char* xrow = Xsb + k * BDUP_K;
#pragma unroll
                for (int j = 0; j < 8; j++)
                    bd[j] = *(const u64*)(xrow + j * 136 + tx * 8);
#pragma unroll
                for (int ip = 0; ip < 4; ip++)
#pragma unroll
                    for (int j = 0; j < 8; j++)
                        FMA2(acc2[ip][j], a2[ip], bd[j]);
            }
            __syncthreads();
        }

#pragma unroll
        for (int ip = 0; ip < 4; ip++) {
#pragma unroll
            for (int j = 0; j < 8; j++) {
                float2 p = unpack2(acc2[ip][j]);
                Sc[(ty * 8 + ip * 2) * 129 + tx * 8 + j]     = p.x;
                Sc[(ty * 8 + ip * 2 + 1) * 129 + tx * 8 + j] = p.y;
            }
        }
        __syncthreads();

        if (tid < 128) {   // running top-16, (score desc, idx asc)
            const float* scr = Sc + tid * 129;
            float* tv = topv + tid * NK;
            int*   ti = topi + tid * NK;
            float th = tv[NK - 1];
            int  thi = ti[NK - 1];
            for (int p = 0; p < 128; p++) {
                float s = scr[p] - hn_s[p];
                int gi = xbase + p;
                if (s > th || (s == th && gi < thi)) {
                    int r = NK - 1;
                    while (r > 0) {
                        float pv = tv[r - 1];
                        int   pi = ti[r - 1];
                        if (s > pv || (s == pv && gi < pi)) {
                            tv[r] = pv; ti[r] = pi; r--;
                        } else break;
                    }
                    tv[r] = s; ti[r] = gi;
                    th = tv[NK - 1]; thi = ti[NK - 1];
                }
            }
        }
        __syncthreads();
    }

    if (tid < 128) {
        int q = cloud * NS + qt * 128 + tid;
#pragma unroll
        for (int r = 0; r < NK; r++) {
            g_knnv[((size_t)q * SEG + sg) * NK + r] = topv[tid * NK + r];
            g_knni[((size_t)q * SEG + sg) * NK + r] = topi[tid * NK + r];
        }
    }
}

// ===================== merge + gather =====================
__global__ __launch_bounds__(256) void merge_kernel() {
    int q = blockIdx.x * 256 + threadIdx.x;
    if (q >= NQ) return;
    const float* v  = g_knnv + (size_t)q * SEG * NK;
    const int*   ii = g_knni + (size_t)q * SEG * NK;
    unsigned long long used = 0ull;
    for (int r = 0; r < NK; r++) {
        float bv = NEG_INF; int bi = 0x7fffffff, bs = 0;
        for (int j = 0; j < SEG * NK; j++) {
            if ((used >> j) & 1ull) continue;
            float vv = v[j]; int vi = ii[j];
            if (vv > bv || (vv == bv && vi < bi)) { bv = vv; bi = vi; bs = j; }
        }
        used |= 1ull << bs;
        g_nn[(size_t)q * NK + r] = bi;
    }
}

__global__ __launch_bounds__(128) void gather_kernel(float* __restrict__ out) {
    __shared__ int nn[NK];
    const int q = blockIdx.x, tid = threadIdx.x;
    if (tid < NK) nn[tid] = g_nn[(size_t)q * NK + tid];
    __syncthreads();
    float mx[4] = {NEG_INF, NEG_INF, NEG_INF, NEG_INF};
    float mn[4] = {POS_INF, POS_INF, POS_INF, POS_INF};
#pragma unroll
    for (int n = 0; n < NK; n++) {
        const float* hp = g_h + (size_t)nn[n] * NO;
#pragma unroll
        for (int j = 0; j < 4; j++) {
            float v = hp[tid + j * 128];
            mx[j] = fmaxf(mx[j], v); mn[j] = fminf(mn[j], v);
        }
    }
    float* op = out + (size_t)q * NO;
#pragma unroll
    for (int j = 0; j < 4; j++) {
        int c = tid + j * 128;
        float a = g_a[c], cc = g_c[c];
        float o = fmaxf(fmaf(a, mx[j], cc), fmaf(a, mn[j], cc));
        op[c] = fmaxf(o, 0.0f);
    }
}

// ===================== launch =====================
extern "C" void kernel_launch(void* const* d_in, const int* in_sizes, int n_in,
                              void* d_out, int out_size) {
    (void)in_sizes; (void)n_in; (void)out_size;
    const float* features  = (const float*)d_in[0];
    const float* positions = (const float*)d_in[1];
    const int*   batch     = (const int*)d_in[2];
    const float* W         = (const float*)d_in[3];
    const float* bias      = (const float*)d_in[4];
    const float* gamma     = (const float*)d_in[5];
    const float* beta      = (const float*)d_in[6];

    float* out       = (float*)d_out;
    float* out_feat  = out;
    float* out_pos   = out + (size_t)NQ * NO;
    float* out_batch = out_pos + (size_t)NQ * 3;

    cudaFuncSetAttribute(fused_kernel, cudaFuncAttributeMaxDynamicSharedMemorySize, FUSED_SMEM);
    cudaFuncSetAttribute(knn_kernel, cudaFuncAttributeMaxDynamicSharedMemorySize, KNN_SMEM);

    fused_kernel<<<16 + 2048, 256, FUSED_SMEM>>>(features, positions, batch, W, bias,
                                                 out_pos, out_batch);
    stats_partial_kernel<<<128, 512>>>();
    stats_final_kernel<<<1, 512>>>(gamma, beta);
    knn_kernel<<<dim3(8, SEG, NB), 256, KNN_SMEM>>>(features);   // 4th launch -> ncu
    merge_kernel<<<NQ / 256, 256>>>();
    gather_kernel<<<NQ, 128>>>(out_feat);
}